// round 17
// baseline (speedup 1.0000x reference)
#include <cuda_runtime.h>
#include <math.h>

// Problem constants (fixed by reference setup)
#define BD     16      // batch
#define HD     16      // heads
#define DD     128     // head dim
#define BLKD   16      // tokens per cache block
#define MAXBD  128     // blocks per sequence
#define MAXSD  2048    // max sequence length
#define NSPLIT 16      // token splits per (b,h)
#define CHUNK  128     // tokens per split
#define WTOK   32      // contiguous tokens per warp
#define SOFTMAX_SCALE 0.088388347648318447f  // 1/sqrt(128)
#define NEGBIG (-1e30f)
// L2-residency partition: blocks with (e & 15) < PINBLK loaded with
// 256-bit ld.global.nc.L2::evict_last (highest retention priority),
// the rest evict_first. ~98MB pinned < 126MB L2.
#define PINBLK 6

// Partial-result scratch (allocation-free: __device__ globals, zero-init .bss)
__device__ float g_pm[BD * HD * NSPLIT];
__device__ float g_pl[BD * HD * NSPLIT];
__device__ float g_pacc[BD * HD * NSPLIT * DD];      // 2 MB
__device__ unsigned int g_cnt[BD * HD];              // self-resetting counters

// ---- 256-bit cache-hinted loads (sm_100+: hint requires v8.b32) ------------
__device__ __forceinline__ void ld256_last(const float* p, float v[8]) {
    unsigned r0,r1,r2,r3,r4,r5,r6,r7;
    asm volatile("ld.global.nc.L2::evict_last.v8.b32 {%0,%1,%2,%3,%4,%5,%6,%7}, [%8];"
        : "=r"(r0),"=r"(r1),"=r"(r2),"=r"(r3),"=r"(r4),"=r"(r5),"=r"(r6),"=r"(r7)
        : "l"(p));
    v[0]=__uint_as_float(r0); v[1]=__uint_as_float(r1);
    v[2]=__uint_as_float(r2); v[3]=__uint_as_float(r3);
    v[4]=__uint_as_float(r4); v[5]=__uint_as_float(r5);
    v[6]=__uint_as_float(r6); v[7]=__uint_as_float(r7);
}
__device__ __forceinline__ void ld256_first(const float* p, float v[8]) {
    unsigned r0,r1,r2,r3,r4,r5,r6,r7;
    asm volatile("ld.global.nc.L2::evict_first.v8.b32 {%0,%1,%2,%3,%4,%5,%6,%7}, [%8];"
        : "=r"(r0),"=r"(r1),"=r"(r2),"=r"(r3),"=r"(r4),"=r"(r5),"=r"(r6),"=r"(r7)
        : "l"(p));
    v[0]=__uint_as_float(r0); v[1]=__uint_as_float(r1);
    v[2]=__uint_as_float(r2); v[3]=__uint_as_float(r3);
    v[4]=__uint_as_float(r4); v[5]=__uint_as_float(r5);
    v[6]=__uint_as_float(r6); v[7]=__uint_as_float(r7);
}

// ---------------------------------------------------------------------------
// Split-KV decode attention: 256-bit loads (1KB/instr) + evict_last pinning.
//  grid (NSPLIT, HD, BD), 128 threads = 4 warps; warp w owns contiguous
//  tokens [s0+32w, +32). Half-warp layout: lane&15 -> 8-float slice of D;
//  lane>>4 -> token parity. One v8.b32 load = 32 lanes x 32B = 1KB
//  contiguous (2 full K rows). 4 tokens / 4 load instrs per iteration.
//  Two online-softmax states per warp (one per half), merged via shfl 16.
//  RoPE'd q (scaled), RoPE'd k, and fresh V staged in SMEM by warp 0.
//  Pinned blocks ((e&15)<PINBLK): evict_last; rest evict_first.
//  Empty splits write no scratch; combiner uses nvalid = ceil(L/CHUNK).
//  Last split CTA per (b,h) combines & writes output, resets counter.
// ---------------------------------------------------------------------------
__global__ __launch_bounds__(128, 7) void attn_fused(
    const float* __restrict__ Q,  const float* __restrict__ K,
    const float* __restrict__ V,  const float* __restrict__ Kc,
    const float* __restrict__ Vc, const float* __restrict__ cosb,
    const float* __restrict__ sinb, const float* __restrict__ mask,
    const int* __restrict__ ilen, const int* __restrict__ btab,
    float* __restrict__ out)
{
    __shared__ float sq[DD], sk[DD], sv[DD];
    __shared__ float sm_m[4], sm_l[4], sm_a[4 * DD];
    __shared__ unsigned s_last;

    const int split = blockIdx.x, h = blockIdx.y, b = blockIdx.z;
    const int tid = threadIdx.x, warp = tid >> 5, lane = tid & 31;
    const int bh   = b * HD + h;
    const int pidx = bh * NSPLIT + split;
    const int L  = ilen[b];
    const int s0 = split * CHUNK;

    if (s0 < L) {
        const int s1  = (s0 + CHUNK < L) ? s0 + CHUNK : L;
        const int pos = L - 1;   // fresh-token position

        // --- warp 0 stages RoPE'd q (scaled), k, and fresh V in SMEM ---
        if (warp == 0) {
            const float4 q4  = *(const float4*)(Q    + bh * DD + 4 * lane);
            const float4 k4  = *(const float4*)(K    + bh * DD + 4 * lane);
            const float4 vv4 = *(const float4*)(V    + bh * DD + 4 * lane);
            const float4 c4  = *(const float4*)(cosb + b * DD + 4 * lane);
            const float4 s4  = *(const float4*)(sinb + b * DD + 4 * lane);
            const float sgn = (lane < 16) ? -1.f : 1.f;   // rot = [-x2, x1]
            float4 qp, kp;
            qp.x = __shfl_xor_sync(~0u, q4.x, 16);  qp.y = __shfl_xor_sync(~0u, q4.y, 16);
            qp.z = __shfl_xor_sync(~0u, q4.z, 16);  qp.w = __shfl_xor_sync(~0u, q4.w, 16);
            kp.x = __shfl_xor_sync(~0u, k4.x, 16);  kp.y = __shfl_xor_sync(~0u, k4.y, 16);
            kp.z = __shfl_xor_sync(~0u, k4.z, 16);  kp.w = __shfl_xor_sync(~0u, k4.w, 16);
            float4 qr, kr;
            qr.x = (q4.x * c4.x + sgn * qp.x * s4.x) * SOFTMAX_SCALE;
            qr.y = (q4.y * c4.y + sgn * qp.y * s4.y) * SOFTMAX_SCALE;
            qr.z = (q4.z * c4.z + sgn * qp.z * s4.z) * SOFTMAX_SCALE;
            qr.w = (q4.w * c4.w + sgn * qp.w * s4.w) * SOFTMAX_SCALE;
            kr.x =  k4.x * c4.x + sgn * kp.x * s4.x;
            kr.y =  k4.y * c4.y + sgn * kp.y * s4.y;
            kr.z =  k4.z * c4.z + sgn * kp.z * s4.z;
            kr.w =  k4.w * c4.w + sgn * kp.w * s4.w;
            ((float4*)sq)[lane] = qr;
            ((float4*)sk)[lane] = kr;
            ((float4*)sv)[lane] = vv4;
        }
        __syncthreads();

        const int hl   = lane & 15;   // 8-float slice index of D
        const int half = lane >> 4;   // token parity within pair

        float q8[8];
        #pragma unroll
        for (int i = 0; i < 8; i++) q8[i] = sq[8 * hl + i];

        const float* mk  = mask + b * MAXSD;
        const int    ws0 = s0 + WTOK * warp;          // warp's first token

        float m = NEGBIG, l = 0.f;
        float acc[8];
        #pragma unroll
        for (int i = 0; i < 8; i++) acc[i] = 0.f;

        if (ws0 < s1) {
            const int* bt = btab + b * MAXBD;
            const int  e0 = __ldg(bt + (ws0 >> 4));
            const int  e1 = __ldg(bt + (ws0 >> 4) + 1);

            #pragma unroll
            for (int u = 0; u < 8; u++) {
                const int tb = ws0 + 4 * u;           // 4 tokens this iter
                if (tb >= s1) break;                  // warp-uniform exit

                const int  e   = (u < 4) ? e0 : e1;
                const bool pin = (e & 15) < PINBLK;
                const int  ta  = tb + half;           // tokens tb, tb+1
                const int  tb2 = tb + 2 + half;       // tokens tb+2, tb+3
                // tb&15 in {0,4,8,12}: all 4 tokens in block e
                const int offa = ((e * BLKD + (ta  & 15)) * HD + h) * DD + 8 * hl;
                const int offb = ((e * BLKD + (tb2 & 15)) * HD + h) * DD + 8 * hl;

                float ka[8], va[8], kb[8], vb[8];
                if (pin) {
                    ld256_last(Kc + offa, ka);  ld256_last(Vc + offa, va);
                    ld256_last(Kc + offb, kb);  ld256_last(Vc + offb, vb);
                } else {
                    ld256_first(Kc + offa, ka); ld256_first(Vc + offa, va);
                    ld256_first(Kc + offb, kb); ld256_first(Vc + offb, vb);
                }
                if (ta == pos) {
                    #pragma unroll
                    for (int i = 0; i < 8; i++) { ka[i] = sk[8*hl+i]; va[i] = sv[8*hl+i]; }
                }
                if (tb2 == pos) {
                    #pragma unroll
                    for (int i = 0; i < 8; i++) { kb[i] = sk[8*hl+i]; vb[i] = sv[8*hl+i]; }
                }

                float da = 0.f, db = 0.f;
                #pragma unroll
                for (int i = 0; i < 8; i++) { da += q8[i] * ka[i]; db += q8[i] * kb[i]; }
                #pragma unroll
                for (int o = 8; o > 0; o >>= 1) {     // half-warp reduce
                    da += __shfl_xor_sync(~0u, da, o);
                    db += __shfl_xor_sync(~0u, db, o);
                }
                const float mka = __ldg(mk + ta);     // always < MAXSD, safe
                const float mkb = __ldg(mk + tb2);
                const float sa = (ta  < s1) ? da + mka : NEGBIG;
                const float sb = (tb2 < s1) ? db + mkb : NEGBIG;

                const float gm   = fmaxf(sa, sb);
                const float mnew = fmaxf(m, gm);
                const float corr = __expf(m - mnew);
                float pa = __expf(sa - mnew); if (ta  >= s1) pa = 0.f;
                float pb = __expf(sb - mnew); if (tb2 >= s1) pb = 0.f;
                l = l * corr + pa + pb;
                #pragma unroll
                for (int i = 0; i < 8; i++)
                    acc[i] = acc[i] * corr + pa * va[i] + pb * vb[i];
                m = mnew;
            }
        }

        // --- merge the two half-warp states (shfl 16) ---
        {
            const float mo = __shfl_xor_sync(~0u, m, 16);
            const float lo = __shfl_xor_sync(~0u, l, 16);
            const float M2 = fmaxf(m, mo);
            const float wa = __expf(m  - M2);   // both-empty: exp(0)=1, l=0 ok
            const float wb = __expf(mo - M2);
            l = l * wa + lo * wb;
            #pragma unroll
            for (int i = 0; i < 8; i++) {
                const float ao = __shfl_xor_sync(~0u, acc[i], 16);
                acc[i] = acc[i] * wa + ao * wb;
            }
            m = M2;
        }

        // --- combine the 4 warps' partials ---
        if (half == 0) {
            #pragma unroll
            for (int i = 0; i < 8; i++) sm_a[warp * DD + 8 * hl + i] = acc[i];
        }
        if (lane == 0) { sm_m[warp] = m; sm_l[warp] = l; }
        __syncthreads();

        const float M = fmaxf(fmaxf(sm_m[0], sm_m[1]), fmaxf(sm_m[2], sm_m[3]));
        float Lt = 0.f, a = 0.f;
        #pragma unroll
        for (int w = 0; w < 4; w++) {
            const float wl = sm_l[w];
            const float wf = (wl > 0.f) ? __expf(sm_m[w] - M) : 0.f;
            Lt += wf * wl;
            a  += wf * sm_a[w * DD + tid];
        }
        if (tid == 0) { g_pm[pidx] = M; g_pl[pidx] = Lt; }
        g_pacc[pidx * DD + tid] = a;
    }
    // empty splits write NOTHING: combiner uses nvalid = ceil(L/CHUNK)

    // --- threadfence reduction: last split CTA combines & writes output ---
    __threadfence();
    __syncthreads();
    if (tid == 0)
        s_last = (atomicAdd(&g_cnt[bh], 1u) == NSPLIT - 1u) ? 1u : 0u;
    __syncthreads();

    if (s_last) {
        const int nvalid = (L + CHUNK - 1) / CHUNK;   // valid splits for bh
        const int base   = bh * NSPLIT;

        float M = NEGBIG;
        for (int i = 0; i < nvalid; i++) M = fmaxf(M, g_pm[base + i]);

        float Lt = 0.f, a = 0.f;
        for (int i = 0; i < nvalid; i++) {
            const float w = __expf(g_pm[base + i] - M);
            Lt += w * g_pl[base + i];
            a  += w * g_pacc[(base + i) * DD + tid];
        }
        out[bh * DD + tid] = a / Lt;
        if (tid == 0) g_cnt[bh] = 0u;   // self-reset for next graph replay
    }
}

// ---------------------------------------------------------------------------
extern "C" void kernel_launch(void* const* d_in, const int* in_sizes, int n_in,
                              void* d_out, int out_size)
{
    const float* Q    = (const float*)d_in[0];
    const float* K    = (const float*)d_in[1];
    const float* V    = (const float*)d_in[2];
    const float* Kc   = (const float*)d_in[3];
    const float* Vc   = (const float*)d_in[4];
    const float* cosb = (const float*)d_in[5];
    const float* sinb = (const float*)d_in[6];
    const float* mask = (const float*)d_in[7];
    const int*   ilen = (const int*)d_in[8];
    // d_in[9] = save_slots — unused (fresh token is at input_length-1)
    const int*   btab = (const int*)d_in[10];
    (void)in_sizes; (void)n_in; (void)out_size;

    dim3 g1(NSPLIT, HD, BD);
    attn_fused<<<g1, 128>>>(Q, K, V, Kc, Vc, cosb, sinb, mask, ilen, btab,
                            (float*)d_out);
}